// round 6
// baseline (speedup 1.0000x reference)
#include <cuda_runtime.h>
#include <cuda_bf16.h>
#include <cstdint>

#define NUM_PINS_MAX   2000000
#define MAX_BLOCKS     4096
#define CHUNK_QUADS    128          // quads per warp steal (4 iters/lane)

// Scratch: packed (x,y) per pin, per-block partials, counters.
__device__ float2       g_pinxy[NUM_PINS_MAX];
__device__ double       g_partials[MAX_BLOCKS];
__device__ unsigned int g_counter = 0;   // last-block reduction counter
__device__ unsigned int g_work    = 0;   // work-stealing chunk counter

// ---------------------------------------------------------------------------
// Kernel A: pack x/y halves of pin_pos into float2 array, 4 pins per thread.
// Also resets the work-stealing counter for this replay (stream-ordered
// before the main kernel -> deterministic under graph capture).
// g_pinxy address taken in DEVICE code only (host-side __device__ symbol ref
// silently hits ATS host shadow memory on GB300).
// ---------------------------------------------------------------------------
__global__ void __launch_bounds__(256)
pack_pins_kernel(const float4* __restrict__ x4,
                 const float4* __restrict__ y4,
                 int n4)                      // n_pins / 4
{
    if (blockIdx.x == 0 && threadIdx.x == 0) {
        g_work = 0;
    }
    float4* __restrict__ out4 = reinterpret_cast<float4*>(g_pinxy);
    int i = blockIdx.x * blockDim.x + threadIdx.x;
    if (i < n4) {
        float4 x = x4[i];
        float4 y = y4[i];
        out4[2 * i]     = make_float4(x.x, y.x, x.y, y.y);
        out4[2 * i + 1] = make_float4(x.z, y.z, x.w, y.w);
    }
}

// ---------------------------------------------------------------------------
// Kernel B: main pair loop with WARP-LEVEL WORK STEALING.
// Each warp atomically grabs CHUNK_QUADS contiguous quads at a time:
// preserves per-warp streaming coalescing while letting fast warps absorb
// the work of L1tex-queue-delayed ones (kills the multi-CTA tail spread).
// Fused last-block final reduction.
// ---------------------------------------------------------------------------
__global__ void __launch_bounds__(256)
pair_attraction_kernel(const int4*   __restrict__ pairs4,   // [n_quads] (a0,b0,a1,b1)
                       const float2* __restrict__ w2,       // [n_quads]
                       int n_quads,
                       float* __restrict__ out)
{
    const float2* __restrict__ pinxy = g_pinxy;

    int lane = threadIdx.x & 31;
    int wid  = threadIdx.x >> 5;

    float acc0 = 0.0f, acc1 = 0.0f;

    while (true) {
        unsigned int chunk;
        if (lane == 0) chunk = atomicAdd(&g_work, 1u);
        chunk = __shfl_sync(0xFFFFFFFFu, chunk, 0);

        int base = (int)(chunk * CHUNK_QUADS);
        if (base >= n_quads) break;
        int end = min(base + CHUNK_QUADS, n_quads);

        for (int i = base + lane; i < end; i += 32) {
            // streaming loads, evict-first, coalesced within the warp
            int4   p = __ldcs(&pairs4[i]);
            float2 w = __ldcs(&w2[i]);

            float2 a0 = __ldg(&pinxy[p.x]);
            float2 b0 = __ldg(&pinxy[p.y]);
            float2 a1 = __ldg(&pinxy[p.z]);
            float2 b1 = __ldg(&pinxy[p.w]);

            float dx0 = a0.x - b0.x, dy0 = a0.y - b0.y;
            float dx1 = a1.x - b1.x, dy1 = a1.y - b1.y;

            acc0 = fmaf(w.x, fmaf(dx0, dx0, dy0 * dy0), acc0);
            acc1 = fmaf(w.y, fmaf(dx1, dx1, dy1 * dy1), acc1);
        }
    }

    float acc = acc0 + acc1;

    // warp reduce (fp32)
    #pragma unroll
    for (int off = 16; off > 0; off >>= 1)
        acc += __shfl_xor_sync(0xFFFFFFFFu, acc, off);

    // block reduce via shared (double for cross-warp combine)
    __shared__ double warp_sums[8];   // 256 threads = 8 warps
    if (lane == 0) warp_sums[wid] = (double)acc;
    __syncthreads();

    if (wid == 0) {
        double v = (lane < 8) ? warp_sums[lane] : 0.0;
        #pragma unroll
        for (int off = 4; off > 0; off >>= 1)
            v += __shfl_xor_sync(0xFFFFFFFFu, v, off);
        if (lane == 0) g_partials[blockIdx.x] = v;
    }

    // ---- last-block final reduction ----
    __shared__ bool is_last;
    if (threadIdx.x == 0) {
        __threadfence();  // make this block's partial visible
        unsigned int old = atomicAdd(&g_counter, 1u);
        is_last = (old == gridDim.x - 1);
    }
    __syncthreads();

    if (is_last) {
        __threadfence();  // acquire: see all other blocks' partials
        double v = 0.0;
        for (int i = threadIdx.x; i < (int)gridDim.x; i += blockDim.x)
            v += g_partials[i];

        #pragma unroll
        for (int off = 16; off > 0; off >>= 1)
            v += __shfl_xor_sync(0xFFFFFFFFu, v, off);

        __shared__ double fin[8];
        if (lane == 0) fin[wid] = v;
        __syncthreads();

        if (wid == 0) {
            double s = (lane < 8) ? fin[lane] : 0.0;
            #pragma unroll
            for (int off = 4; off > 0; off >>= 1)
                s += __shfl_xor_sync(0xFFFFFFFFu, s, off);
            if (lane == 0) {
                out[0] = (float)s;
                g_counter = 0;   // reset for next graph replay (deterministic)
            }
        }
    }
}

// ---------------------------------------------------------------------------
// Launcher
// ---------------------------------------------------------------------------
extern "C" void kernel_launch(void* const* d_in, const int* in_sizes, int n_in,
                              void* d_out, int out_size) {
    const float* pin_pos = (const float*)d_in[0];
    const float* weights = (const float*)d_in[1];
    const int*   pairs   = (const int*)d_in[2];
    // d_in[3] = pin_mask (unused by the reference computation)

    int n_pins  = in_sizes[0] / 2;          // 2,000,000
    int n_pairs = in_sizes[2] / 2;          // 10,000,000
    int n_quads = n_pairs / 2;              // 5,000,000

    float* out = (float*)d_out;

    // A: pack pins (vectorized, 4 pins/thread) + reset work counter
    {
        int n4      = n_pins / 4;           // 500,000
        int threads = 256;
        int blocks  = (n4 + threads - 1) / threads;
        pack_pins_kernel<<<blocks, threads>>>(
            (const float4*)pin_pos,
            (const float4*)(pin_pos + n_pins),
            n4);
    }

    // B: main loop (work stealing) + fused final reduction
    int threads = 256;
    int blocks  = 148 * 8;                  // 1184 blocks = one full wave
    if (blocks > MAX_BLOCKS) blocks = MAX_BLOCKS;
    pair_attraction_kernel<<<blocks, threads>>>(
        (const int4*)pairs, (const float2*)weights, n_quads, out);
}

// round 7
// speedup vs baseline: 1.0225x; 1.0225x over previous
#include <cuda_runtime.h>
#include <cuda_bf16.h>
#include <cstdint>

#define NUM_PINS_MAX   2000000
#define MAX_BLOCKS     4096

// Scratch: packed (x,y) per pin, per-block partials, reduction counter.
__device__ float2       g_pinxy[NUM_PINS_MAX];
__device__ double       g_partials[MAX_BLOCKS];
__device__ unsigned int g_counter = 0;

// ---------------------------------------------------------------------------
// Kernel A: pack x/y halves of pin_pos into float2 array, 4 pins per thread.
// g_pinxy address taken in DEVICE code only (host-side __device__ symbol ref
// silently hits ATS host shadow memory on GB300).
// ---------------------------------------------------------------------------
__global__ void __launch_bounds__(256)
pack_pins_kernel(const float4* __restrict__ x4,
                 const float4* __restrict__ y4,
                 int n4)                      // n_pins / 4
{
    float4* __restrict__ out4 = reinterpret_cast<float4*>(g_pinxy);
    int i = blockIdx.x * blockDim.x + threadIdx.x;
    if (i < n4) {
        float4 x = x4[i];
        float4 y = y4[i];
        out4[2 * i]     = make_float4(x.x, y.x, x.y, y.y);
        out4[2 * i + 1] = make_float4(x.z, y.z, x.w, y.w);
    }
}

// ---------------------------------------------------------------------------
// Kernel B: main pair loop — identical hot loop to the best (R5) kernel:
// ONE quad per iteration (4 gathers + 2 streaming loads in flight).
// Tail fixed by launching 3 waves of CTAs: waves >= 2 are placed by the HW
// CLC work-stealing scheduler, so fast SMs absorb the slack of
// L1tex-queue-delayed ones with zero hot-loop overhead.
// Fused last-block final reduction.
// ---------------------------------------------------------------------------
__global__ void __launch_bounds__(256)
pair_attraction_kernel(const int4*   __restrict__ pairs4,   // [n_quads] (a0,b0,a1,b1)
                       const float2* __restrict__ w2,       // [n_quads]
                       int n_quads,
                       float* __restrict__ out)
{
    const float2* __restrict__ pinxy = g_pinxy;

    float acc0 = 0.0f, acc1 = 0.0f;
    int stride = gridDim.x * blockDim.x;

    for (int i = blockIdx.x * blockDim.x + threadIdx.x; i < n_quads; i += stride) {
        // streaming loads, evict-first, fully coalesced within each warp
        int4   p = __ldcs(&pairs4[i]);
        float2 w = __ldcs(&w2[i]);

        float2 a0 = __ldg(&pinxy[p.x]);
        float2 b0 = __ldg(&pinxy[p.y]);
        float2 a1 = __ldg(&pinxy[p.z]);
        float2 b1 = __ldg(&pinxy[p.w]);

        float dx0 = a0.x - b0.x, dy0 = a0.y - b0.y;
        float dx1 = a1.x - b1.x, dy1 = a1.y - b1.y;

        acc0 = fmaf(w.x, fmaf(dx0, dx0, dy0 * dy0), acc0);
        acc1 = fmaf(w.y, fmaf(dx1, dx1, dy1 * dy1), acc1);
    }

    float acc = acc0 + acc1;

    // warp reduce (fp32)
    #pragma unroll
    for (int off = 16; off > 0; off >>= 1)
        acc += __shfl_xor_sync(0xFFFFFFFFu, acc, off);

    // block reduce via shared (double for cross-warp combine)
    __shared__ double warp_sums[8];   // 256 threads = 8 warps
    int lane = threadIdx.x & 31;
    int wid  = threadIdx.x >> 5;
    if (lane == 0) warp_sums[wid] = (double)acc;
    __syncthreads();

    if (wid == 0) {
        double v = (lane < 8) ? warp_sums[lane] : 0.0;
        #pragma unroll
        for (int off = 4; off > 0; off >>= 1)
            v += __shfl_xor_sync(0xFFFFFFFFu, v, off);
        if (lane == 0) g_partials[blockIdx.x] = v;
    }

    // ---- last-block final reduction ----
    __shared__ bool is_last;
    if (threadIdx.x == 0) {
        __threadfence();  // make this block's partial visible
        unsigned int old = atomicAdd(&g_counter, 1u);
        is_last = (old == gridDim.x - 1);
    }
    __syncthreads();

    if (is_last) {
        __threadfence();  // acquire: see all other blocks' partials
        double v = 0.0;
        for (int i = threadIdx.x; i < (int)gridDim.x; i += blockDim.x)
            v += g_partials[i];

        #pragma unroll
        for (int off = 16; off > 0; off >>= 1)
            v += __shfl_xor_sync(0xFFFFFFFFu, v, off);

        __shared__ double fin[8];
        if (lane == 0) fin[wid] = v;
        __syncthreads();

        if (wid == 0) {
            double s = (lane < 8) ? fin[lane] : 0.0;
            #pragma unroll
            for (int off = 4; off > 0; off >>= 1)
                s += __shfl_xor_sync(0xFFFFFFFFu, s, off);
            if (lane == 0) {
                out[0] = (float)s;
                g_counter = 0;   // reset for next graph replay (deterministic)
            }
        }
    }
}

// ---------------------------------------------------------------------------
// Launcher
// ---------------------------------------------------------------------------
extern "C" void kernel_launch(void* const* d_in, const int* in_sizes, int n_in,
                              void* d_out, int out_size) {
    const float* pin_pos = (const float*)d_in[0];
    const float* weights = (const float*)d_in[1];
    const int*   pairs   = (const int*)d_in[2];
    // d_in[3] = pin_mask (unused by the reference computation)

    int n_pins  = in_sizes[0] / 2;          // 2,000,000
    int n_pairs = in_sizes[2] / 2;          // 10,000,000
    int n_quads = n_pairs / 2;              // 5,000,000

    float* out = (float*)d_out;

    // A: pack pins (vectorized, 4 pins/thread)
    {
        int n4      = n_pins / 4;           // 500,000
        int threads = 256;
        int blocks  = (n4 + threads - 1) / threads;
        pack_pins_kernel<<<blocks, threads>>>(
            (const float4*)pin_pos,
            (const float4*)(pin_pos + n_pins),
            n4);
    }

    // B: main loop, 3 waves -> CLC work-stealing balances the tail
    int threads = 256;
    int blocks  = 148 * 8 * 3;              // 3552 blocks = 3 waves @ occ 8
    if (blocks > MAX_BLOCKS) blocks = MAX_BLOCKS;
    pair_attraction_kernel<<<blocks, threads>>>(
        (const int4*)pairs, (const float2*)weights, n_quads, out);
}

// round 8
// speedup vs baseline: 1.1181x; 1.0934x over previous
#include <cuda_runtime.h>
#include <cuda_bf16.h>
#include <cstdint>

#define NUM_PINS_MAX   2000000
#define MAX_BLOCKS     8192

// Scratch: packed (x,y) per pin, per-block partials, counters.
__device__ float2       g_pinxy[NUM_PINS_MAX];
__device__ double       g_partials[MAX_BLOCKS];
__device__ unsigned int g_counter = 0;   // last-block reduction counter
__device__ unsigned int g_done    = 0;   // pack-phase barrier counter

// ---------------------------------------------------------------------------
// Single persistent kernel (exactly ONE resident wave — grid sized via the
// occupancy API in the launcher, so the inter-phase spin barrier cannot
// deadlock).
//  Phase 1: pack x/y halves of pin_pos into float2 (contiguous slice per CTA)
//  Phase 2: device-wide barrier (counter + fences)
//  Phase 3: pair loop, identical to the best-measured (R5) hot loop
//  Phase 4: block reduce + last-block final reduction; counters reset
// g_pinxy address is only ever taken in device code (host-side __device__
// symbol ref silently hits ATS host shadow memory on GB300).
// ---------------------------------------------------------------------------
__global__ void __launch_bounds__(256, 8)
fused_attraction_kernel(const float4* __restrict__ x4,     // pin_pos[0:n)
                        const float4* __restrict__ y4,     // pin_pos[n:2n)
                        int n4,                            // n_pins/4
                        const int4*   __restrict__ pairs4, // [n_quads]
                        const float2* __restrict__ w2,     // [n_quads]
                        int n_quads,
                        float* __restrict__ out)
{
    const int tid    = threadIdx.x;
    const int lane   = tid & 31;
    const int wid    = tid >> 5;
    const int stride = gridDim.x * blockDim.x;

    // ---- Phase 1: pack pins (grid-stride, coalesced) ----
    {
        float4* __restrict__ out4 = reinterpret_cast<float4*>(g_pinxy);
        for (int i = blockIdx.x * blockDim.x + tid; i < n4; i += stride) {
            float4 x = x4[i];
            float4 y = y4[i];
            out4[2 * i]     = make_float4(x.x, y.x, x.y, y.y);
            out4[2 * i + 1] = make_float4(x.z, y.z, x.w, y.w);
        }
    }

    // ---- Phase 2: device-wide barrier (all CTAs are resident) ----
    __syncthreads();                 // all threads in CTA finished packing
    if (tid == 0) {
        __threadfence();             // release: publish this CTA's packs
        atomicAdd(&g_done, 1u);
        while (atomicAdd(&g_done, 0u) < gridDim.x) {
            __nanosleep(64);
        }
        __threadfence();             // acquire: see all CTAs' packs
    }
    __syncthreads();                 // propagate acquire to whole CTA

    // ---- Phase 3: pair loop (R5 hot loop, unchanged) ----
    const float2* __restrict__ pinxy = g_pinxy;

    float acc0 = 0.0f, acc1 = 0.0f;
    for (int i = blockIdx.x * blockDim.x + tid; i < n_quads; i += stride) {
        int4   p = __ldcs(&pairs4[i]);
        float2 w = __ldcs(&w2[i]);

        float2 a0 = __ldg(&pinxy[p.x]);
        float2 b0 = __ldg(&pinxy[p.y]);
        float2 a1 = __ldg(&pinxy[p.z]);
        float2 b1 = __ldg(&pinxy[p.w]);

        float dx0 = a0.x - b0.x, dy0 = a0.y - b0.y;
        float dx1 = a1.x - b1.x, dy1 = a1.y - b1.y;

        acc0 = fmaf(w.x, fmaf(dx0, dx0, dy0 * dy0), acc0);
        acc1 = fmaf(w.y, fmaf(dx1, dx1, dy1 * dy1), acc1);
    }

    float acc = acc0 + acc1;

    // ---- Phase 4: reductions ----
    #pragma unroll
    for (int off = 16; off > 0; off >>= 1)
        acc += __shfl_xor_sync(0xFFFFFFFFu, acc, off);

    __shared__ double warp_sums[8];   // 256 threads = 8 warps
    if (lane == 0) warp_sums[wid] = (double)acc;
    __syncthreads();

    if (wid == 0) {
        double v = (lane < 8) ? warp_sums[lane] : 0.0;
        #pragma unroll
        for (int off = 4; off > 0; off >>= 1)
            v += __shfl_xor_sync(0xFFFFFFFFu, v, off);
        if (lane == 0) g_partials[blockIdx.x] = v;
    }

    __shared__ bool is_last;
    if (tid == 0) {
        __threadfence();  // make this block's partial visible
        unsigned int old = atomicAdd(&g_counter, 1u);
        is_last = (old == gridDim.x - 1);
    }
    __syncthreads();

    if (is_last) {
        __threadfence();  // acquire: see all other blocks' partials
        double v = 0.0;
        for (int i = tid; i < (int)gridDim.x; i += blockDim.x)
            v += g_partials[i];

        #pragma unroll
        for (int off = 16; off > 0; off >>= 1)
            v += __shfl_xor_sync(0xFFFFFFFFu, v, off);

        __shared__ double fin[8];
        if (lane == 0) fin[wid] = v;
        __syncthreads();

        if (wid == 0) {
            double s = (lane < 8) ? fin[lane] : 0.0;
            #pragma unroll
            for (int off = 4; off > 0; off >>= 1)
                s += __shfl_xor_sync(0xFFFFFFFFu, s, off);
            if (lane == 0) {
                out[0]    = (float)s;
                g_counter = 0;   // reset for next replay (stream-ordered)
                g_done    = 0;
            }
        }
    }
}

// ---------------------------------------------------------------------------
// Launcher: ONE kernel, grid = exactly one resident wave (occupancy API keeps
// the spin barrier deadlock-free on any SM count / reg allocation).
// ---------------------------------------------------------------------------
extern "C" void kernel_launch(void* const* d_in, const int* in_sizes, int n_in,
                              void* d_out, int out_size) {
    const float* pin_pos = (const float*)d_in[0];
    const float* weights = (const float*)d_in[1];
    const int*   pairs   = (const int*)d_in[2];
    // d_in[3] = pin_mask (unused by the reference computation)

    int n_pins  = in_sizes[0] / 2;          // 2,000,000
    int n_pairs = in_sizes[2] / 2;          // 10,000,000
    int n_quads = n_pairs / 2;              // 5,000,000
    int n4      = n_pins / 4;               // 500,000

    float* out = (float*)d_out;

    int threads = 256;
    int nsm = 0, occ = 0;
    cudaDeviceGetAttribute(&nsm, cudaDevAttrMultiProcessorCount, 0);
    cudaOccupancyMaxActiveBlocksPerMultiprocessor(
        &occ, fused_attraction_kernel, threads, 0);
    if (nsm <= 0) nsm = 148;
    if (occ <= 0) occ = 1;
    int blocks = nsm * occ;                 // exactly one resident wave
    if (blocks > MAX_BLOCKS) blocks = MAX_BLOCKS;

    fused_attraction_kernel<<<blocks, threads>>>(
        (const float4*)pin_pos,
        (const float4*)(pin_pos + n_pins),
        n4,
        (const int4*)pairs, (const float2*)weights, n_quads,
        out);
}